// round 10
// baseline (speedup 1.0000x reference)
#include <cuda_runtime.h>
#include <cuda_bf16.h>
#include <cstdint>

// ---------------- problem constants ----------------
constexpr int B_ROWS = 16384;
constexpr int D      = 2048;
constexpr int N_TOP  = 8;
constexpr int N_CLS  = 16;
constexpr int N_OUT  = 128;
constexpr int NC     = 136;          // 8 top + 128 bottom
constexpr int NTILES = 17;           // 17 x n8
constexpr int KSTEPS = D / 16;       // 128

constexpr int BM      = 128;
constexpr int THREADS = 512;         // 16 warps: wy=wid&3 (32 rows), wx=wid>>2 (tiles)
constexpr int LPITCH  = 137;
constexpr int STEP_U4 = NTILES * 32; // 544 uint4 per kstep of packed W

// CTA-shared pipeline staging (deduped: each A/B byte copied ONCE per CTA)
constexpr int DEPTH     = 3;                     // stages; prefetch distance 2
constexpr int A_BYTES   = BM * 64;               // 128 rows x 16 f32 = 8192
constexpr int B_BYTES   = NTILES * 512;          // 8704
constexpr int STAGE     = A_BYTES + B_BYTES + 512;   // 17408, pad keeps 512-align
constexpr int SMEM_PIPE = DEPTH * STAGE;         // 52224
constexpr int SMEM_L    = BM * LPITCH * (int)sizeof(float);  // 70144
constexpr int SMEM      = (SMEM_PIPE > SMEM_L) ? SMEM_PIPE : SMEM_L;

// Packed weights, fragment layout with k-permutation (same as R7/R8):
// lane(g=lane>>2, q=lane&3) of tile t, kstep s holds cols 4q..4q+3 of n=t*8+g
// as uint4 {b01hi, b23hi, b01lo, b23lo}.
__device__ uint4 g_Wp[KSTEPS * STEP_U4];
__device__ float g_bc[NC];

// ---------------- helpers ----------------
__device__ __forceinline__ void rsplit2(float x, float y, uint32_t& hi, uint32_t& lo) {
    __nv_bfloat162 h = __float22bfloat162_rn(make_float2(x, y));
    float2 hf = __bfloat1622float2(h);
    __nv_bfloat162 l = __float22bfloat162_rn(make_float2(x - hf.x, y - hf.y));
    hi = *reinterpret_cast<uint32_t*>(&h);
    lo = *reinterpret_cast<uint32_t*>(&l);
}
__device__ __forceinline__ void tsplit2(float x, float y, uint32_t& hi, uint32_t& lo) {
    uint32_t xu = __float_as_uint(x), yu = __float_as_uint(y);
    hi = __byte_perm(xu, yu, 0x7632);
    float lx = x - __uint_as_float(xu & 0xFFFF0000u);
    float ly = y - __uint_as_float(yu & 0xFFFF0000u);
    __nv_bfloat162 l = __float22bfloat162_rn(make_float2(lx, ly));
    lo = *reinterpret_cast<uint32_t*>(&l);
}

__device__ __forceinline__ uint32_t smem_u32(const void* p) {
    uint32_t a;
    asm("{ .reg .u64 t; cvta.to.shared.u64 t, %1; cvt.u32.u64 %0, t; }" : "=r"(a) : "l"(p));
    return a;
}
__device__ __forceinline__ void cpa16(uint32_t dst, const void* src) {
    asm volatile("cp.async.cg.shared.global [%0], [%1], 16;" :: "r"(dst), "l"(src) : "memory");
}
#define CPA_COMMIT() asm volatile("cp.async.commit_group;" ::: "memory")
#define CPA_WAIT2()  asm volatile("cp.async.wait_group 2;" ::: "memory")

__device__ __forceinline__ float4 lds_f4(uint32_t a) {
    float4 v;
    asm volatile("ld.shared.v4.f32 {%0,%1,%2,%3}, [%4];"
                 : "=f"(v.x), "=f"(v.y), "=f"(v.z), "=f"(v.w) : "r"(a));
    return v;
}
__device__ __forceinline__ uint4 lds_u4(uint32_t a) {
    uint4 v;
    asm volatile("ld.shared.v4.b32 {%0,%1,%2,%3}, [%4];"
                 : "=r"(v.x), "=r"(v.y), "=r"(v.z), "=r"(v.w) : "r"(a));
    return v;
}

#define MMA16816(c, a0, a1, a2, a3, b0, b1) \
    asm volatile("mma.sync.aligned.m16n8k16.row.col.f32.bf16.bf16.f32 " \
        "{%0,%1,%2,%3}, {%4,%5,%6,%7}, {%8,%9}, {%0,%1,%2,%3};" \
        : "+f"((c)[0]), "+f"((c)[1]), "+f"((c)[2]), "+f"((c)[3]) \
        : "r"(a0), "r"(a1), "r"(a2), "r"(a3), "r"(b0), "r"(b1))

// ---------------------------------------------------------------------------
// Pack W (k-permuted fragment layout), rn split.
// ---------------------------------------------------------------------------
__device__ __forceinline__ float wval(const float* __restrict__ topW,
                                      const float* __restrict__ botW,
                                      int n, int k) {
    if (n < N_TOP) return topW[n * D + k];
    int m = n - 8;
    return botW[((m >> 4) * D + k) * N_CLS + (m & 15)];
}

__global__ void pack_kernel(const float* __restrict__ topW,
                            const float* __restrict__ topb,
                            const float* __restrict__ botW,
                            const float* __restrict__ botb) {
    int idx = blockIdx.x * blockDim.x + threadIdx.x;
    if (idx < NC) g_bc[idx] = (idx < N_TOP) ? topb[idx] : botb[idx - 8];
    if (idx >= KSTEPS * STEP_U4) return;

    int lane = idx & 31;
    int t    = (idx >> 5) % NTILES;
    int s    = idx / STEP_U4;
    int g = lane >> 2, q = lane & 3;
    int n  = t * 8 + g;
    int k0 = s * 16 + 4 * q;

    float x0 = wval(topW, botW, n, k0);
    float x1 = wval(topW, botW, n, k0 + 1);
    float x2 = wval(topW, botW, n, k0 + 2);
    float x3 = wval(topW, botW, n, k0 + 3);

    uint32_t h01, l01, h23, l23;
    rsplit2(x0, x1, h01, l01);
    rsplit2(x2, x3, h23, l23);
    g_Wp[idx] = make_uint4(h01, h23, l01, l23);
}

// ---------------------------------------------------------------------------
// Main kernel: CTA-deduped cp.async pipeline (1 barrier/kstep, distance 2) +
// pass-major split-bf16 HMMA + gate/softmax epilogue.
// Stage layout: [A: 128 rows x 64B][B: 17 tiles x 512B].
// ---------------------------------------------------------------------------
__global__ __launch_bounds__(THREADS, 1)
void hier_mma_kernel(const float* __restrict__ A, float* __restrict__ out) {
    extern __shared__ char smem[];
    float* L = reinterpret_cast<float*>(smem);
    const uint32_t sb = smem_u32(smem);

    const int tid  = threadIdx.x;
    const int lane = tid & 31;
    const int wid  = tid >> 5;
    const int wy   = wid & 3;               // SMSP id: each SMSP gets wx=0..3
    const int wx   = wid >> 2;
    const int g    = lane >> 2;
    const int q    = lane & 3;
    const int rowBase = blockIdx.x * BM;

    const int  tbase = wx * 4;
    const bool extra = (wx == 0);           // tile 16

    // --- copy-duty mapping (each byte of A/B copied once per CTA) ---
    // A: thread t copies 16B: row = t>>2 (0..127), quad = t&3 -> dst row*64+quad*16
    const uint32_t aDst = sb + (uint32_t)(tid >> 2) * 64 + (uint32_t)(tid & 3) * 16;
    const float*   aSrc0 = A + (size_t)(rowBase + (tid >> 2)) * D + (tid & 3) * 4;
    // B: thread t copies uint4 u=t; threads 0..31 also u=512+t
    const uint32_t bDst0 = sb + A_BYTES + (uint32_t)tid * 16;
    const uint32_t bDst1 = sb + A_BYTES + (uint32_t)(512 + tid) * 16;
    const bool bSecond = (tid < STEP_U4 - 512);   // tid < 32

    // --- compute-side bases ---
    const uint32_t aRd = sb + (uint32_t)(wy * 32 + g) * 64 + (uint32_t)q * 16;
    const uint32_t bRd = sb + A_BYTES + (uint32_t)tbase * 512 + (uint32_t)lane * 16;
    const uint32_t bRdE = sb + A_BYTES + 16u * 512 + (uint32_t)lane * 16;

    float acc[4][8], accE[8];
#pragma unroll
    for (int t = 0; t < 4; ++t)
#pragma unroll
        for (int j = 0; j < 8; ++j) acc[t][j] = 0.0f;
#pragma unroll
    for (int j = 0; j < 8; ++j) accE[j] = 0.0f;

    auto issue = [&](int s, int st) {
        cpa16(aDst + st * STAGE, aSrc0 + (size_t)s * 16);
        const uint4* ws = g_Wp + (size_t)s * STEP_U4;
        cpa16(bDst0 + st * STAGE, ws + tid);
        if (bSecond) cpa16(bDst1 + st * STAGE, ws + 512 + tid);
    };

    // ---- prologue: ksteps 0,1 in flight ----
    issue(0, 0); CPA_COMMIT();
    issue(1, 1); CPA_COMMIT();

#pragma unroll 3
    for (int s = 0; s < KSTEPS; ++s) {
        // prefetch kstep s+2 into slot (s+2)%3 (its readers finished at barrier s-1)
        if (s + 2 < KSTEPS) issue(s + 2, (s + 2) % DEPTH);
        CPA_COMMIT();           // uniform group count (possibly empty)
        CPA_WAIT2();            // own copies for kstep s complete
        __syncthreads();        // all threads' copies for s visible; prev reads done

        const uint32_t stoff = (uint32_t)((s % DEPTH) * STAGE);

        // A fragments: rows wy*32+g+{0,8,16,24}, 16B each (conflict-free)
        float4 x0 = lds_f4(aRd + stoff);
        float4 x1 = lds_f4(aRd + stoff + 8 * 64);
        float4 x2 = lds_f4(aRd + stoff + 16 * 64);
        float4 x3 = lds_f4(aRd + stoff + 24 * 64);

        uint4 bc[4];
#pragma unroll
        for (int tt = 0; tt < 4; ++tt) bc[tt] = lds_u4(bRd + stoff + tt * 512);
        uint4 bcE = extra ? lds_u4(bRdE + stoff) : bc[0];

        // split A into hi/lo fragments
        uint32_t ahi[8], alo[8];
        tsplit2(x0.x, x0.y, ahi[0], alo[0]);  tsplit2(x0.z, x0.w, ahi[1], alo[1]);
        tsplit2(x1.x, x1.y, ahi[2], alo[2]);  tsplit2(x1.z, x1.w, ahi[3], alo[3]);
        tsplit2(x2.x, x2.y, ahi[4], alo[4]);  tsplit2(x2.z, x2.w, ahi[5], alo[5]);
        tsplit2(x3.x, x3.y, ahi[6], alo[6]);  tsplit2(x3.z, x3.w, ahi[7], alo[7]);

        // pass-major MMA ordering (same-acc reuse distance ~9-10)
        // pass 0: hi * b.xy
#pragma unroll
        for (int tt = 0; tt < 4; ++tt)
            MMA16816(acc[tt],     ahi[0], ahi[2], ahi[1], ahi[3], bc[tt].x, bc[tt].y);
        if (extra) MMA16816(accE, ahi[0], ahi[2], ahi[1], ahi[3], bcE.x, bcE.y);
#pragma unroll
        for (int tt = 0; tt < 4; ++tt)
            MMA16816(acc[tt] + 4, ahi[4], ahi[6], ahi[5], ahi[7], bc[tt].x, bc[tt].y);
        if (extra) MMA16816(accE + 4, ahi[4], ahi[6], ahi[5], ahi[7], bcE.x, bcE.y);
        // pass 1: lo * b.xy
#pragma unroll
        for (int tt = 0; tt < 4; ++tt)
            MMA16816(acc[tt],     alo[0], alo[2], alo[1], alo[3], bc[tt].x, bc[tt].y);
        if (extra) MMA16816(accE, alo[0], alo[2], alo[1], alo[3], bcE.x, bcE.y);
#pragma unroll
        for (int tt = 0; tt < 4; ++tt)
            MMA16816(acc[tt] + 4, alo[4], alo[6], alo[5], alo[7], bc[tt].x, bc[tt].y);
        if (extra) MMA16816(accE + 4, alo[4], alo[6], alo[5], alo[7], bcE.x, bcE.y);
        // pass 2: hi * b.zw
#pragma unroll
        for (int tt = 0; tt < 4; ++tt)
            MMA16816(acc[tt],     ahi[0], ahi[2], ahi[1], ahi[3], bc[tt].z, bc[tt].w);
        if (extra) MMA16816(accE, ahi[0], ahi[2], ahi[1], ahi[3], bcE.z, bcE.w);
#pragma unroll
        for (int tt = 0; tt < 4; ++tt)
            MMA16816(acc[tt] + 4, ahi[4], ahi[6], ahi[5], ahi[7], bc[tt].z, bc[tt].w);
        if (extra) MMA16816(accE + 4, ahi[4], ahi[6], ahi[5], ahi[7], bcE.z, bcE.w);
    }

    __syncthreads();   // pipeline dead; smem becomes logits

    // ---- stage logits (+bias) into smem ----
#pragma unroll
    for (int tt = 0; tt < 5; ++tt) {
        const float* ac;
        int t;
        if (tt < 4) { ac = acc[tt]; t = tbase + tt; }
        else if (extra) { ac = accE; t = 16; }
        else break;
        int c = t * 8 + 2 * q;
        float b0 = g_bc[c], b1 = g_bc[c + 1];
#pragma unroll
        for (int h = 0; h < 2; ++h) {
            int r = wy * 32 + h * 16 + g;
            L[r * LPITCH + c]           = ac[4 * h + 0] + b0;
            L[r * LPITCH + c + 1]       = ac[4 * h + 1] + b1;
            L[(r + 8) * LPITCH + c]     = ac[4 * h + 2] + b0;
            L[(r + 8) * LPITCH + c + 1] = ac[4 * h + 3] + b1;
        }
    }
    __syncthreads();

    // ---- per-row: sigmoid gate + 8x softmax(16), in place ----
    if (tid < BM) {
        float* Lr = L + tid * LPITCH;
#pragma unroll
        for (int t = 0; t < N_TOP; ++t) {
            float gate = 1.0f / (1.0f + __expf(-Lr[t]));
            float* gr = Lr + 8 + t * N_CLS;
            float m = gr[0];
#pragma unroll
            for (int c = 1; c < N_CLS; ++c) m = fmaxf(m, gr[c]);
            float e[N_CLS];
            float sum = 0.0f;
#pragma unroll
            for (int c = 0; c < N_CLS; ++c) { e[c] = __expf(gr[c] - m); sum += e[c]; }
            float inv = gate / sum;
#pragma unroll
            for (int c = 0; c < N_CLS; ++c) gr[c] = e[c] * inv;
        }
    }
    __syncthreads();

    // ---- coalesced writeback 128x128 ----
    for (int idx = tid; idx < BM * N_OUT; idx += THREADS) {
        int r = idx >> 7, c = idx & 127;
        out[(size_t)(rowBase + r) * N_OUT + c] = L[r * LPITCH + 8 + c];
    }
}

// ---------------------------------------------------------------------------
extern "C" void kernel_launch(void* const* d_in, const int* in_sizes, int n_in,
                              void* d_out, int out_size) {
    const float* features = (const float*)d_in[0];
    const float* top_W    = (const float*)d_in[1];
    const float* top_b    = (const float*)d_in[2];
    const float* bottom_W = (const float*)d_in[3];
    const float* bottom_b = (const float*)d_in[4];
    float* out = (float*)d_out;

    {
        int total = KSTEPS * STEP_U4;
        int threads = 256;
        pack_kernel<<<(total + threads - 1) / threads, threads>>>(
            top_W, top_b, bottom_W, bottom_b);
    }
    cudaFuncSetAttribute(hier_mma_kernel,
                         cudaFuncAttributeMaxDynamicSharedMemorySize, SMEM);
    hier_mma_kernel<<<B_ROWS / BM, THREADS, SMEM>>>(features, out);
}

// round 13
// speedup vs baseline: 1.1503x; 1.1503x over previous
#include <cuda_runtime.h>
#include <cuda_bf16.h>
#include <cstdint>

// ---------------- problem constants ----------------
constexpr int B_ROWS = 16384;
constexpr int D      = 2048;
constexpr int N_TOP  = 8;
constexpr int N_CLS  = 16;
constexpr int N_OUT  = 128;
constexpr int NC     = 136;          // 8 top + 128 bottom
constexpr int NTILES = 17;           // 17 x n8
constexpr int KSTEPS = D / 16;       // 128

constexpr int BM      = 128;
constexpr int THREADS = 512;         // 16 warps: wy=wid&3 (rows), wx=wid>>2 (tiles)
constexpr int LPITCH  = 137;
constexpr int STEP_U4 = NTILES * 32; // 544 uint4 per kstep

// per-warp private pipeline staging (R8 structure)
constexpr int DEPTH   = 3;           // stages; prefetch distance 2
constexpr int A_STAGE = 2048;        // 32 rows x 64B per kstep
constexpr int B_STAGE = 2560;        // 5 tiles x 512B per kstep
constexpr int SMEM_PIPE = 16 * DEPTH * (A_STAGE + B_STAGE);        // 221184
constexpr int SMEM_L    = BM * LPITCH * (int)sizeof(float);        // 70144
constexpr int SMEM      = (SMEM_PIPE > SMEM_L) ? SMEM_PIPE : SMEM_L;

// Packed weights, fragment layout with k-permutation (same as R7/R8):
// lane(g=lane>>2, q=lane&3) of tile t, kstep s holds cols 4q..4q+3 of n=t*8+g
// as uint4 {b01hi, b23hi, b01lo, b23lo}.
__device__ uint4 g_Wp[KSTEPS * STEP_U4];
__device__ float g_bc[NC];

// ---------------- helpers ----------------
__device__ __forceinline__ void rsplit2(float x, float y, uint32_t& hi, uint32_t& lo) {
    __nv_bfloat162 h = __float22bfloat162_rn(make_float2(x, y));
    float2 hf = __bfloat1622float2(h);
    __nv_bfloat162 l = __float22bfloat162_rn(make_float2(x - hf.x, y - hf.y));
    hi = *reinterpret_cast<uint32_t*>(&h);
    lo = *reinterpret_cast<uint32_t*>(&l);
}
__device__ __forceinline__ void tsplit2(float x, float y, uint32_t& hi, uint32_t& lo) {
    uint32_t xu = __float_as_uint(x), yu = __float_as_uint(y);
    hi = __byte_perm(xu, yu, 0x7632);
    float lx = x - __uint_as_float(xu & 0xFFFF0000u);
    float ly = y - __uint_as_float(yu & 0xFFFF0000u);
    __nv_bfloat162 l = __float22bfloat162_rn(make_float2(lx, ly));
    lo = *reinterpret_cast<uint32_t*>(&l);
}

__device__ __forceinline__ uint32_t smem_u32(const void* p) {
    uint32_t a;
    asm("{ .reg .u64 t; cvta.to.shared.u64 t, %1; cvt.u32.u64 %0, t; }" : "=r"(a) : "l"(p));
    return a;
}
__device__ __forceinline__ void cpa16(uint32_t dst, const void* src) {
    asm volatile("cp.async.cg.shared.global [%0], [%1], 16;" :: "r"(dst), "l"(src) : "memory");
}
#define CPA_COMMIT() asm volatile("cp.async.commit_group;" ::: "memory")
#define CPA_WAIT1()  asm volatile("cp.async.wait_group 1;" ::: "memory")

__device__ __forceinline__ float4 lds_f4(uint32_t a) {
    float4 v;
    asm volatile("ld.shared.v4.f32 {%0,%1,%2,%3}, [%4];"
                 : "=f"(v.x), "=f"(v.y), "=f"(v.z), "=f"(v.w) : "r"(a));
    return v;
}
__device__ __forceinline__ uint4 lds_u4(uint32_t a) {
    uint4 v;
    asm volatile("ld.shared.v4.b32 {%0,%1,%2,%3}, [%4];"
                 : "=r"(v.x), "=r"(v.y), "=r"(v.z), "=r"(v.w) : "r"(a));
    return v;
}

#define MMA16816(c, a0, a1, a2, a3, b0, b1) \
    asm volatile("mma.sync.aligned.m16n8k16.row.col.f32.bf16.bf16.f32 " \
        "{%0,%1,%2,%3}, {%4,%5,%6,%7}, {%8,%9}, {%0,%1,%2,%3};" \
        : "+f"((c)[0]), "+f"((c)[1]), "+f"((c)[2]), "+f"((c)[3]) \
        : "r"(a0), "r"(a1), "r"(a2), "r"(a3), "r"(b0), "r"(b1))

// ---------------------------------------------------------------------------
// Pack W (k-permuted fragment layout), rn split.
// ---------------------------------------------------------------------------
__device__ __forceinline__ float wval(const float* __restrict__ topW,
                                      const float* __restrict__ botW,
                                      int n, int k) {
    if (n < N_TOP) return topW[n * D + k];
    int m = n - 8;
    return botW[((m >> 4) * D + k) * N_CLS + (m & 15)];
}

__global__ void pack_kernel(const float* __restrict__ topW,
                            const float* __restrict__ topb,
                            const float* __restrict__ botW,
                            const float* __restrict__ botb) {
    int idx = blockIdx.x * blockDim.x + threadIdx.x;
    if (idx < NC) g_bc[idx] = (idx < N_TOP) ? topb[idx] : botb[idx - 8];
    if (idx >= KSTEPS * STEP_U4) return;

    int lane = idx & 31;
    int t    = (idx >> 5) % NTILES;
    int s    = idx / STEP_U4;
    int g = lane >> 2, q = lane & 3;
    int n  = t * 8 + g;
    int k0 = s * 16 + 4 * q;

    float x0 = wval(topW, botW, n, k0);
    float x1 = wval(topW, botW, n, k0 + 1);
    float x2 = wval(topW, botW, n, k0 + 2);
    float x3 = wval(topW, botW, n, k0 + 3);

    uint32_t h01, l01, h23, l23;
    rsplit2(x0, x1, h01, l01);
    rsplit2(x2, x3, h23, l23);
    g_Wp[idx] = make_uint4(h01, h23, l01, l23);
}

// ---------------------------------------------------------------------------
// Main kernel: per-warp private cp.async pipeline (no barriers), with the
// wait/LDS/split for kstep s+1 software-pipelined under kstep s's MMA passes.
// ---------------------------------------------------------------------------
__global__ __launch_bounds__(THREADS, 1)
void hier_mma_kernel(const float* __restrict__ A, float* __restrict__ out) {
    extern __shared__ char smem[];
    float* L = reinterpret_cast<float*>(smem);
    const uint32_t sb = smem_u32(smem);

    const int tid  = threadIdx.x;
    const int lane = tid & 31;
    const int wid  = tid >> 5;
    const int wy   = wid & 3;               // SMSP id; wx spreads per SMSP
    const int wx   = wid >> 2;
    const int g    = lane >> 2;
    const int q    = lane & 3;
    const int rowBase = blockIdx.x * BM;

    const int  tbase = wx * 4;
    const bool extra = (wx == 0);           // tile 16

    const uint32_t warpA = sb + (uint32_t)wid * (DEPTH * A_STAGE);
    const uint32_t warpB = sb + 16u * DEPTH * A_STAGE + (uint32_t)wid * (DEPTH * B_STAGE);

    // A: rows rowBase + wy*32 + g + {0,8,16,24}, cols 4q.. (+16 per kstep)
    const float* ap = A + (size_t)(rowBase + wy * 32 + g) * D + 4 * q;

    float acc[4][8], accE[8];
#pragma unroll
    for (int t = 0; t < 4; ++t)
#pragma unroll
        for (int j = 0; j < 8; ++j) acc[t][j] = 0.0f;
#pragma unroll
    for (int j = 0; j < 8; ++j) accE[j] = 0.0f;

    auto issue = [&](int s, int st) {
        const float* as = ap + (size_t)s * 16;
#pragma unroll
        for (int r = 0; r < 4; ++r)
            cpa16(warpA + st * A_STAGE + r * 512 + lane * 16, as + (size_t)r * 8 * D);
        const uint4* ws = g_Wp + (size_t)s * STEP_U4 + tbase * 32 + lane;
#pragma unroll
        for (int tt = 0; tt < 4; ++tt)
            cpa16(warpB + st * B_STAGE + tt * 512 + lane * 16, ws + tt * 32);
        if (extra)
            cpa16(warpB + st * B_STAGE + 2048 + lane * 16,
                  g_Wp + (size_t)s * STEP_U4 + 16 * 32 + lane);
    };

    // ---- prologue: ksteps 0,1 in flight; split kstep 0 ----
    issue(0, 0); CPA_COMMIT();
    issue(1, 1); CPA_COMMIT();
    CPA_WAIT1();                        // group 0 complete

    uint32_t ahi[8], alo[8], ahiN[8];
    {
        const uint32_t aa = warpA + lane * 16;
        float4 x0 = lds_f4(aa);
        float4 x1 = lds_f4(aa + 8 * 64);
        float4 x2 = lds_f4(aa + 16 * 64);
        float4 x3 = lds_f4(aa + 24 * 64);
        tsplit2(x0.x, x0.y, ahi[0], alo[0]);  tsplit2(x0.z, x0.w, ahi[1], alo[1]);
        tsplit2(x1.x, x1.y, ahi[2], alo[2]);  tsplit2(x1.z, x1.w, ahi[3], alo[3]);
        tsplit2(x2.x, x2.y, ahi[4], alo[4]);  tsplit2(x2.z, x2.w, ahi[5], alo[5]);
        tsplit2(x3.x, x3.y, ahi[6], alo[6]);  tsplit2(x3.z, x3.w, ahi[7], alo[7]);
    }

#pragma unroll 3
    for (int s = 0; s < KSTEPS; ++s) {
        // prefetch kstep s+2 (slot distinct from both live stages)
        if (s + 2 < KSTEPS) issue(s + 2, (s + 2) % DEPTH);
        CPA_COMMIT();           // uniform group accounting (possibly empty)

        // B for kstep s (group s already complete since last iter's wait)
        const uint32_t stoff = (uint32_t)((s % DEPTH) * 1);   // folded below
        const uint32_t ba = warpB + (s % DEPTH) * B_STAGE + lane * 16;
        uint4 bc[4];
#pragma unroll
        for (int tt = 0; tt < 4; ++tt) bc[tt] = lds_u4(ba + tt * 512);
        uint4 bcE = extra ? lds_u4(ba + 2048) : bc[0];
        (void)stoff;

        // ---- pass 0: hi * b.xy ----
#pragma unroll
        for (int tt = 0; tt < 4; ++tt)
            MMA16816(acc[tt],     ahi[0], ahi[2], ahi[1], ahi[3], bc[tt].x, bc[tt].y);
        if (extra) MMA16816(accE, ahi[0], ahi[2], ahi[1], ahi[3], bcE.x, bcE.y);
#pragma unroll
        for (int tt = 0; tt < 4; ++tt)
            MMA16816(acc[tt] + 4, ahi[4], ahi[6], ahi[5], ahi[7], bc[tt].x, bc[tt].y);
        if (extra) MMA16816(accE + 4, ahi[4], ahi[6], ahi[5], ahi[7], bcE.x, bcE.y);

        // ---- wait s+1 copies; LDS next A (latency hidden under pass 1/2) ----
        CPA_WAIT1();
        float4 x0, x1, x2, x3;
        if (s + 1 < KSTEPS) {
            const uint32_t aa = warpA + ((s + 1) % DEPTH) * A_STAGE + lane * 16;
            x0 = lds_f4(aa);
            x1 = lds_f4(aa + 8 * 64);
            x2 = lds_f4(aa + 16 * 64);
            x3 = lds_f4(aa + 24 * 64);
        }

        // ---- pass 1: lo * b.xy (last use of alo(s)) ----
#pragma unroll
        for (int tt = 0; tt < 4; ++tt)
            MMA16816(acc[tt],     alo[0], alo[2], alo[1], alo[3], bc[tt].x, bc[tt].y);
        if (extra) MMA16816(accE, alo[0], alo[2], alo[1], alo[3], bcE.x, bcE.y);
#pragma unroll
        for (int tt = 0; tt < 4; ++tt)
            MMA16816(acc[tt] + 4, alo[4], alo[6], alo[5], alo[7], bc[tt].x, bc[tt].y);
        if (extra) MMA16816(accE + 4, alo[4], alo[6], alo[5], alo[7], bcE.x, bcE.y);

        // ---- split s+1 (alo overwritten in place; hi into ahiN) ----
        if (s + 1 < KSTEPS) {
            tsplit2(x0.x, x0.y, ahiN[0], alo[0]);  tsplit2(x0.z, x0.w, ahiN[1], alo[1]);
            tsplit2(x1.x, x1.y, ahiN[2], alo[2]);  tsplit2(x1.z, x1.w, ahiN[3], alo[3]);
            tsplit2(x2.x, x2.y, ahiN[4], alo[4]);  tsplit2(x2.z, x2.w, ahiN[5], alo[5]);
            tsplit2(x3.x, x3.y, ahiN[6], alo[6]);  tsplit2(x3.z, x3.w, ahiN[7], alo[7]);
        }

        // ---- pass 2: hi * b.zw (last use of ahi(s)) ----
#pragma unroll
        for (int tt = 0; tt < 4; ++tt)
            MMA16816(acc[tt],     ahi[0], ahi[2], ahi[1], ahi[3], bc[tt].z, bc[tt].w);
        if (extra) MMA16816(accE, ahi[0], ahi[2], ahi[1], ahi[3], bcE.z, bcE.w);
#pragma unroll
        for (int tt = 0; tt < 4; ++tt)
            MMA16816(acc[tt] + 4, ahi[4], ahi[6], ahi[5], ahi[7], bc[tt].z, bc[tt].w);
        if (extra) MMA16816(accE + 4, ahi[4], ahi[6], ahi[5], ahi[7], bcE.z, bcE.w);

        // rotate (renamed away under unroll)
#pragma unroll
        for (int j = 0; j < 8; ++j) ahi[j] = ahiN[j];
    }

    __syncthreads();   // pipeline dead; smem becomes logits

    // ---- stage logits (+bias) into smem ----
#pragma unroll
    for (int tt = 0; tt < 5; ++tt) {
        const float* ac;
        int t;
        if (tt < 4) { ac = acc[tt]; t = tbase + tt; }
        else if (extra) { ac = accE; t = 16; }
        else break;
        int c = t * 8 + 2 * q;
        float b0 = g_bc[c], b1 = g_bc[c + 1];
#pragma unroll
        for (int h = 0; h < 2; ++h) {
            int r = wy * 32 + h * 16 + g;
            L[r * LPITCH + c]           = ac[4 * h + 0] + b0;
            L[r * LPITCH + c + 1]       = ac[4 * h + 1] + b1;
            L[(r + 8) * LPITCH + c]     = ac[4 * h + 2] + b0;
            L[(r + 8) * LPITCH + c + 1] = ac[4 * h + 3] + b1;
        }
    }
    __syncthreads();

    // ---- per-row: sigmoid gate + 8x softmax(16), in place ----
    if (tid < BM) {
        float* Lr = L + tid * LPITCH;
#pragma unroll
        for (int t = 0; t < N_TOP; ++t) {
            float gate = 1.0f / (1.0f + __expf(-Lr[t]));
            float* gr = Lr + 8 + t * N_CLS;
            float m = gr[0];
#pragma unroll
            for (int c = 1; c < N_CLS; ++c) m = fmaxf(m, gr[c]);
            float e[N_CLS];
            float sum = 0.0f;
#pragma unroll
            for (int c = 0; c < N_CLS; ++c) { e[c] = __expf(gr[c] - m); sum += e[c]; }
            float inv = gate / sum;
#pragma unroll
            for (int c = 0; c < N_CLS; ++c) gr[c] = e[c] * inv;
        }
    }
    __syncthreads();

    // ---- coalesced writeback 128x128 ----
    for (int idx = tid; idx < BM * N_OUT; idx += THREADS) {
        int r = idx >> 7, c = idx & 127;
        out[(size_t)(rowBase + r) * N_OUT + c] = L[r * LPITCH + 8 + c];
    }
}

// ---------------------------------------------------------------------------
extern "C" void kernel_launch(void* const* d_in, const int* in_sizes, int n_in,
                              void* d_out, int out_size) {
    const float* features = (const float*)d_in[0];
    const float* top_W    = (const float*)d_in[1];
    const float* top_b    = (const float*)d_in[2];
    const float* bottom_W = (const float*)d_in[3];
    const float* bottom_b = (const float*)d_in[4];
    float* out = (float*)d_out;

    {
        int total = KSTEPS * STEP_U4;
        int threads = 256;
        pack_kernel<<<(total + threads - 1) / threads, threads>>>(
            top_W, top_b, bottom_W, bottom_b);
    }
    cudaFuncSetAttribute(hier_mma_kernel,
                         cudaFuncAttributeMaxDynamicSharedMemorySize, SMEM);
    hier_mma_kernel<<<B_ROWS / BM, THREADS, SMEM>>>(features, out);
}

// round 14
// speedup vs baseline: 1.4148x; 1.2299x over previous
#include <cuda_runtime.h>
#include <cuda_bf16.h>
#include <cstdint>

// ---------------- problem constants ----------------
constexpr int B_ROWS = 16384;
constexpr int D      = 2048;
constexpr int N_TOP  = 8;
constexpr int N_CLS  = 16;
constexpr int N_OUT  = 128;
constexpr int NC     = 136;          // 8 top + 128 bottom
constexpr int NTILES = 17;           // 17 x n8
constexpr int KSTEPS = D / 16;       // 128

constexpr int BM      = 128;
constexpr int THREADS = 512;         // 16 warps: wy=wid&7 (16 rows), wx=wid>>3 (tiles)
constexpr int LPITCH  = 137;
constexpr int STEP_U4 = NTILES * 32; // 544 uint4 per kstep

// per-warp private staging: A 4-deep (distance 2), B 2-deep (distance 1)
constexpr int A_STAGE = 1024;        // 16 rows x 64B
constexpr int A_DEPTH = 4;
constexpr int B_STAGE = 9 * 512;     // up to 9 tiles
constexpr int B_DEPTH = 2;
constexpr int A_REGION = 16 * A_DEPTH * A_STAGE;    // 65536
constexpr int SMEM_PIPE = A_REGION + 16 * B_DEPTH * B_STAGE;  // 212992
constexpr int SMEM_L    = BM * LPITCH * (int)sizeof(float);   // 70144
constexpr int SMEM      = (SMEM_PIPE > SMEM_L) ? SMEM_PIPE : SMEM_L;

// Packed weights, fragment layout with k-permutation (same as R6+):
// lane(g=lane>>2, q=lane&3) of tile t, kstep s holds cols 4q..4q+3 of n=t*8+g
// as uint4 {b01hi, b23hi, b01lo, b23lo}.
__device__ uint4 g_Wp[KSTEPS * STEP_U4];
__device__ float g_bc[NC];

// ---------------- helpers ----------------
__device__ __forceinline__ void rsplit2(float x, float y, uint32_t& hi, uint32_t& lo) {
    __nv_bfloat162 h = __float22bfloat162_rn(make_float2(x, y));
    float2 hf = __bfloat1622float2(h);
    __nv_bfloat162 l = __float22bfloat162_rn(make_float2(x - hf.x, y - hf.y));
    hi = *reinterpret_cast<uint32_t*>(&h);
    lo = *reinterpret_cast<uint32_t*>(&l);
}
__device__ __forceinline__ void tsplit2(float x, float y, uint32_t& hi, uint32_t& lo) {
    uint32_t xu = __float_as_uint(x), yu = __float_as_uint(y);
    hi = __byte_perm(xu, yu, 0x7632);
    float lx = x - __uint_as_float(xu & 0xFFFF0000u);
    float ly = y - __uint_as_float(yu & 0xFFFF0000u);
    __nv_bfloat162 l = __float22bfloat162_rn(make_float2(lx, ly));
    lo = *reinterpret_cast<uint32_t*>(&l);
}

__device__ __forceinline__ uint32_t smem_u32(const void* p) {
    uint32_t a;
    asm("{ .reg .u64 t; cvta.to.shared.u64 t, %1; cvt.u32.u64 %0, t; }" : "=r"(a) : "l"(p));
    return a;
}
__device__ __forceinline__ void cpa16(uint32_t dst, const void* src) {
    asm volatile("cp.async.cg.shared.global [%0], [%1], 16;" :: "r"(dst), "l"(src) : "memory");
}
#define CPA_COMMIT() asm volatile("cp.async.commit_group;" ::: "memory")
#define CPA_WAIT1()  asm volatile("cp.async.wait_group 1;" ::: "memory")

__device__ __forceinline__ float4 lds_f4(uint32_t a) {
    float4 v;
    asm volatile("ld.shared.v4.f32 {%0,%1,%2,%3}, [%4];"
                 : "=f"(v.x), "=f"(v.y), "=f"(v.z), "=f"(v.w) : "r"(a));
    return v;
}
__device__ __forceinline__ uint4 lds_u4(uint32_t a) {
    uint4 v;
    asm volatile("ld.shared.v4.b32 {%0,%1,%2,%3}, [%4];"
                 : "=r"(v.x), "=r"(v.y), "=r"(v.z), "=r"(v.w) : "r"(a));
    return v;
}

#define MMA16816(c, a0, a1, a2, a3, b0, b1) \
    asm volatile("mma.sync.aligned.m16n8k16.row.col.f32.bf16.bf16.f32 " \
        "{%0,%1,%2,%3}, {%4,%5,%6,%7}, {%8,%9}, {%0,%1,%2,%3};" \
        : "+f"((c)[0]), "+f"((c)[1]), "+f"((c)[2]), "+f"((c)[3]) \
        : "r"(a0), "r"(a1), "r"(a2), "r"(a3), "r"(b0), "r"(b1))

// ---------------------------------------------------------------------------
// Pack W (k-permuted fragment layout), rn split.
// ---------------------------------------------------------------------------
__device__ __forceinline__ float wval(const float* __restrict__ topW,
                                      const float* __restrict__ botW,
                                      int n, int k) {
    if (n < N_TOP) return topW[n * D + k];
    int m = n - 8;
    return botW[((m >> 4) * D + k) * N_CLS + (m & 15)];
}

__global__ void pack_kernel(const float* __restrict__ topW,
                            const float* __restrict__ topb,
                            const float* __restrict__ botW,
                            const float* __restrict__ botb) {
    int idx = blockIdx.x * blockDim.x + threadIdx.x;
    if (idx < NC) g_bc[idx] = (idx < N_TOP) ? topb[idx] : botb[idx - 8];
    if (idx >= KSTEPS * STEP_U4) return;

    int lane = idx & 31;
    int t    = (idx >> 5) % NTILES;
    int s    = idx / STEP_U4;
    int g = lane >> 2, q = lane & 3;
    int n  = t * 8 + g;
    int k0 = s * 16 + 4 * q;

    float x0 = wval(topW, botW, n, k0);
    float x1 = wval(topW, botW, n, k0 + 1);
    float x2 = wval(topW, botW, n, k0 + 2);
    float x3 = wval(topW, botW, n, k0 + 3);

    uint32_t h01, l01, h23, l23;
    rsplit2(x0, x1, h01, l01);
    rsplit2(x2, x3, h23, l23);
    g_Wp[idx] = make_uint4(h01, h23, l01, l23);
}

// ---------------------------------------------------------------------------
// Main kernel: 16-row warps (8 wy x 2 wx), barrier-free per-warp cp.async
// staging, pass-major split-bf16 HMMA, gate/softmax epilogue.
// Every lane copies exactly the bytes it later reads -> no barriers needed.
// ---------------------------------------------------------------------------
__global__ __launch_bounds__(THREADS, 1)
void hier_mma_kernel(const float* __restrict__ A, float* __restrict__ out) {
    extern __shared__ char smem[];
    float* L = reinterpret_cast<float*>(smem);
    const uint32_t sb = smem_u32(smem);

    const int tid  = threadIdx.x;
    const int lane = tid & 31;
    const int wid  = tid >> 5;
    const int wy   = wid & 7;               // 16-row group; SMSP = wid&3 mixes wx
    const int wx   = wid >> 3;              // 0: tiles 0..8 (9), 1: tiles 9..16 (8)
    const int g    = lane >> 2;
    const int q    = lane & 3;
    const int rowBase = blockIdx.x * BM;

    const int  tbase = wx * 9;
    const int  nt    = 9 - wx;              // 9 or 8

    const uint32_t warpA = sb + (uint32_t)wid * (A_DEPTH * A_STAGE);
    const uint32_t warpB = sb + A_REGION + (uint32_t)wid * (B_DEPTH * B_STAGE);

    // A fragment source: rows rowBase + wy*16 + g + {0,8}, cols 4q.. (+16/kstep)
    const float* apr0 = A + (size_t)(rowBase + wy * 16 + g) * D + 4 * q;
    const float* apr1 = apr0 + (size_t)8 * D;

    float acc[9][4];
#pragma unroll
    for (int t = 0; t < 9; ++t)
#pragma unroll
        for (int j = 0; j < 4; ++j) acc[t][j] = 0.0f;

    // lane copies its OWN fragment bytes: A offsets lane*16 and 512+lane*16
    auto issueA = [&](int s, int st) {
        cpa16(warpA + st * A_STAGE + lane * 16,       apr0 + (size_t)s * 16);
        cpa16(warpA + st * A_STAGE + 512 + lane * 16, apr1 + (size_t)s * 16);
    };
    auto issueB = [&](int s, int st) {
        const uint4* ws = g_Wp + (size_t)s * STEP_U4 + tbase * 32 + lane;
#pragma unroll
        for (int tt = 0; tt < 9; ++tt)
            if (tt < nt)
                cpa16(warpB + st * B_STAGE + tt * 512 + lane * 16, ws + tt * 32);
    };

    // ---- prologue: A(0),A(1),B(0) in group G0 ----
    issueA(0, 0);
    issueA(1, 1);
    issueB(0, 0);
    CPA_COMMIT();

#pragma unroll 4
    for (int s = 0; s < KSTEPS; ++s) {
        // group G_{s+1}: A(s+2) and B(s+1)
        if (s + 2 < KSTEPS) issueA(s + 2, (s + 2) & 3);
        if (s + 1 < KSTEPS) issueB(s + 1, (s + 1) & 1);
        CPA_COMMIT();
        CPA_WAIT1();            // G_s done => A(s+1), B(s) complete (own bytes)

        // A fragments (own copied bytes)
        const uint32_t aa = warpA + (s & 3) * A_STAGE + lane * 16;
        float4 x0 = lds_f4(aa);
        float4 x1 = lds_f4(aa + 512);

        // B tiles (own copied bytes)
        const uint32_t ba = warpB + (s & 1) * B_STAGE + lane * 16;
        uint4 bc[9];
#pragma unroll
        for (int tt = 0; tt < 9; ++tt)
            if (tt < nt) bc[tt] = lds_u4(ba + tt * 512);

        // split A into hi/lo fragments (4 tsplit2 only)
        uint32_t ahi[4], alo[4];
        tsplit2(x0.x, x0.y, ahi[0], alo[0]);  tsplit2(x0.z, x0.w, ahi[1], alo[1]);
        tsplit2(x1.x, x1.y, ahi[2], alo[2]);  tsplit2(x1.z, x1.w, ahi[3], alo[3]);

        // pass-major MMAs (reuse distance = nt)
#pragma unroll
        for (int tt = 0; tt < 9; ++tt)
            if (tt < nt)
                MMA16816(acc[tt], ahi[0], ahi[2], ahi[1], ahi[3], bc[tt].x, bc[tt].y);
#pragma unroll
        for (int tt = 0; tt < 9; ++tt)
            if (tt < nt)
                MMA16816(acc[tt], alo[0], alo[2], alo[1], alo[3], bc[tt].x, bc[tt].y);
#pragma unroll
        for (int tt = 0; tt < 9; ++tt)
            if (tt < nt)
                MMA16816(acc[tt], ahi[0], ahi[2], ahi[1], ahi[3], bc[tt].z, bc[tt].w);
    }

    __syncthreads();   // pipeline dead; smem becomes logits

    // ---- stage logits (+bias) into smem ----
#pragma unroll
    for (int tt = 0; tt < 9; ++tt) {
        if (tt < nt) {
            int c = (tbase + tt) * 8 + 2 * q;
            float b0 = g_bc[c], b1 = g_bc[c + 1];
            int r = wy * 16 + g;
            L[r * LPITCH + c]           = acc[tt][0] + b0;
            L[r * LPITCH + c + 1]       = acc[tt][1] + b1;
            L[(r + 8) * LPITCH + c]     = acc[tt][2] + b0;
            L[(r + 8) * LPITCH + c + 1] = acc[tt][3] + b1;
        }
    }
    __syncthreads();

    // ---- per-row: sigmoid gate + 8x softmax(16), in place ----
    if (tid < BM) {
        float* Lr = L + tid * LPITCH;
#pragma unroll
        for (int t = 0; t < N_TOP; ++t) {
            float gate = 1.0f / (1.0f + __expf(-Lr[t]));
            float* gr = Lr + 8 + t * N_CLS;
            float m = gr[0];
#pragma unroll
            for (int c = 1; c < N_CLS; ++c) m = fmaxf(m, gr[c]);
            float e[N_CLS];
            float sum = 0.0f;
#pragma unroll
            for (int c = 0; c < N_CLS; ++c) { e[c] = __expf(gr[c] - m); sum += e[c]; }
            float inv = gate / sum;
#pragma unroll
            for (int c = 0; c < N_CLS; ++c) gr[c] = e[c] * inv;
        }
    }
    __syncthreads();

    // ---- coalesced writeback 128x128 ----
    for (int idx = tid; idx < BM * N_OUT; idx += THREADS) {
        int r = idx >> 7, c = idx & 127;
        out[(size_t)(rowBase + r) * N_OUT + c] = L[r * LPITCH + 8 + c];
    }
}

// ---------------------------------------------------------------------------
extern "C" void kernel_launch(void* const* d_in, const int* in_sizes, int n_in,
                              void* d_out, int out_size) {
    const float* features = (const float*)d_in[0];
    const float* top_W    = (const float*)d_in[1];
    const float* top_b    = (const float*)d_in[2];
    const float* bottom_W = (const float*)d_in[3];
    const float* bottom_b = (const float*)d_in[4];
    float* out = (float*)d_out;

    {
        int total = KSTEPS * STEP_U4;
        int threads = 256;
        pack_kernel<<<(total + threads - 1) / threads, threads>>>(
            top_W, top_b, bottom_W, bottom_b);
    }
    cudaFuncSetAttribute(hier_mma_kernel,
                         cudaFuncAttributeMaxDynamicSharedMemorySize, SMEM);
    hier_mma_kernel<<<B_ROWS / BM, THREADS, SMEM>>>(features, out);
}